// round 8
// baseline (speedup 1.0000x reference)
#include <cuda_runtime.h>

#define TT   1024
#define FF   2048
#define LL   128
#define HH   256
#define GG   384
#define NF   8             // features per CTA (4 pairs)
#define NTH  256
#define NCTA 256           // 2048 / 8  -> 2 CTAs per SM
#define PSTR 6             // pair-stride in u64 (4 pairs + 2 pad)

typedef unsigned long long u64;

// k-major transposed weights, padded for prefetch-ring overrun (no allocation)
__device__ float g_W1t[LL * HH + 2048];   // [k][j]  = W1[j][k]
__device__ float g_W2t[HH * LL + 2048];   // [j][k'] = W2[k'][j]
__device__ float g_Wht[LL * GG + 2048];   // [k][g]  = Whh[g][k]

// shared-memory layout (u64 units)
#define OFF_HS   0                          // h: [k=128][6]    -> 768
#define OFF_A1   768                        // A1: [j=256][6]   -> 1536
#define OFF_SC   2304                       // partial scratch
#define AP_BLK   1280                       // A: [kh=2][jp=128][10]
#define BP_BLK   640                        // B: [jq=4][kp=64][10]
#define CP_BLK   2048                       // C: [kh=2][p=128][16]
#define U64_CNT  6400
#define SMEM_BYTES (U64_CNT * 8 + 64 * 4)   // 51456 B  (2 CTAs/SM fit)

__device__ __forceinline__ u64 pk2(float lo, float hi) {
    u64 r; asm("mov.b64 %0, {%1, %2};" : "=l"(r) : "f"(lo), "f"(hi)); return r;
}
__device__ __forceinline__ float2 up2(u64 v) {
    float2 r; asm("mov.b64 {%0, %1}, %2;" : "=f"(r.x), "=f"(r.y) : "l"(v)); return r;
}
__device__ __forceinline__ u64 fma2(u64 a, u64 b, u64 c) {
    u64 d; asm("fma.rn.f32x2 %0, %1, %2, %3;" : "=l"(d) : "l"(a), "l"(b), "l"(c)); return d;
}
__device__ __forceinline__ u64 add2(u64 a, u64 b) {
    u64 d; asm("add.rn.f32x2 %0, %1, %2;" : "=l"(d) : "l"(a), "l"(b)); return d;
}
__device__ __forceinline__ float sigm(float x) { return 1.0f / (1.0f + expf(-x)); }

__global__ void prep_kernel(const float* __restrict__ W1,
                            const float* __restrict__ W2,
                            const float* __restrict__ Whh) {
    int i = blockIdx.x * blockDim.x + threadIdx.x;
    if (i < HH * LL) { int j = i / LL, k = i % LL; g_W1t[k * HH + j] = W1[i]; }
    if (i < LL * HH) { int k = i / HH, j = i % HH; g_W2t[j * LL + k] = W2[i]; }
    if (i < GG * LL) { int g = i / LL, k = i % LL; g_Wht[k * GG + g] = Whh[i]; }
}

__global__ __launch_bounds__(NTH, 2)
void odernn_kernel(const float* __restrict__ times,
                   const float* __restrict__ vals,
                   const float* __restrict__ mask,
                   const float* __restrict__ b1,
                   const float* __restrict__ b2,
                   const float* __restrict__ Wih,
                   const float* __restrict__ bih,
                   const float* __restrict__ bhh,
                   float* __restrict__ out)
{
    extern __shared__ u64 sm[];
    float* xob = (float*)(sm + U64_CNT);     // 8
    float* xms = (float*)(sm + U64_CNT) + 8;

    const int tid = threadIdx.x;
    const int cta = blockIdx.x;

    for (int i = tid; i < 128 * PSTR; i += NTH) sm[OFF_HS + i] = 0ull;   // h0 = 0

    // thread-resident constants
    const int jp  = tid & 127;           // phase-A j-pair
    const int kh  = tid >> 7;            // k-half (phases A, C)
    const int kp  = tid & 63;            // phase-B k'-pair
    const int jq  = tid >> 6;            // phase-B j-quarter
    const int p   = tid & 127;           // latent index (C / GRU)
    const int fh  = tid >> 7;            // GRU feature-half
    const float bbA = __ldg(b1 + tid);                    // A-reduce bias
    const float bbO = __ldg(b2 + (tid >> 1));             // ODE bias
    const float brg = __ldg(bhh + p), bzg = __ldg(bhh + p + 128), bng = __ldg(bhh + p + 256);
    const float wir = __ldg(Wih + p), wiz = __ldg(Wih + p + 128), win = __ldg(Wih + p + 256);
    const float bir = __ldg(bih + p), biz = __ldg(bih + p + 128), binn = __ldg(bih + p + 256);
    __syncthreads();

    for (int t = 0; t < TT; t++) {
        if (tid < NF) {
            long it = (long)(TT - 1 - t) * FF + (cta * NF + tid);
            xob[tid] = __ldg(vals + it);
            xms[tid] = __ldg(mask + it);
        }
        float dt = 0.0f;
        if (t > 0) dt = __ldg(times + (TT - t)) - __ldg(times + (TT - 1 - t));

        // ---- Phase A: partial a1[f][2jp..] = sum_{k in half} h[f][k]*W1t[k][2jp..]
        {
            const int k0 = kh * 64;
            const float2* w = (const float2*)g_W1t + jp;   // stride 128 float2 per k
            float2 buf[8];
            #pragma unroll
            for (int u = 0; u < 8; u++) buf[u] = __ldg(w + (k0 + u) * 128);
            u64 a0[4], a1v[4];
            #pragma unroll
            for (int i = 0; i < 4; i++) { a0[i] = 0ull; a1v[i] = 0ull; }
            for (int kk = 0; kk < 64; kk += 8) {
                #pragma unroll
                for (int u = 0; u < 8; u++) {
                    float2 wv = buf[u];
                    buf[u] = __ldg(w + (k0 + kk + u + 8) * 128);   // ring prefetch (padded)
                    u64 w0 = pk2(wv.x, wv.x), w1 = pk2(wv.y, wv.y);
                    const u64* hr = sm + OFF_HS + (k0 + kk + u) * PSTR;
                    ulonglong2 hA = *(const ulonglong2*)hr;
                    ulonglong2 hB = *(const ulonglong2*)(hr + 2);
                    a0[0] = fma2(hA.x, w0, a0[0]);  a1v[0] = fma2(hA.x, w1, a1v[0]);
                    a0[1] = fma2(hA.y, w0, a0[1]);  a1v[1] = fma2(hA.y, w1, a1v[1]);
                    a0[2] = fma2(hB.x, w0, a0[2]);  a1v[2] = fma2(hB.x, w1, a1v[2]);
                    a0[3] = fma2(hB.y, w0, a0[3]);  a1v[3] = fma2(hB.y, w1, a1v[3]);
                }
            }
            u64* d = sm + OFF_SC + kh * AP_BLK + jp * 10;
            {
                ulonglong2 s; s.x = a0[0]; s.y = a0[1]; *(ulonglong2*)(d) = s;
            }
            {
                ulonglong2 s; s.x = a0[2]; s.y = a0[3]; *(ulonglong2*)(d + 2) = s;
            }
            {
                ulonglong2 s; s.x = a1v[0]; s.y = a1v[1]; *(ulonglong2*)(d + 4) = s;
            }
            {
                ulonglong2 s; s.x = a1v[2]; s.y = a1v[3]; *(ulonglong2*)(d + 6) = s;
            }
        }
        __syncthreads();

        // ---- A-reduce + tanh -> A1[j][4 pairs]   (j = tid)
        {
            const u64* s0 = sm + OFF_SC + (tid >> 1) * 10 + (tid & 1) * 4;
            ulonglong2 pA = *(const ulonglong2*)s0;
            ulonglong2 pB = *(const ulonglong2*)(s0 + 2);
            ulonglong2 qA = *(const ulonglong2*)(s0 + AP_BLK);
            ulonglong2 qB = *(const ulonglong2*)(s0 + AP_BLK + 2);
            float2 f0 = up2(add2(pA.x, qA.x)), f1 = up2(add2(pA.y, qA.y));
            float2 f2 = up2(add2(pB.x, qB.x)), f3 = up2(add2(pB.y, qB.y));
            ulonglong2 o0, o1;
            o0.x = pk2(tanhf(f0.x + bbA), tanhf(f0.y + bbA));
            o0.y = pk2(tanhf(f1.x + bbA), tanhf(f1.y + bbA));
            o1.x = pk2(tanhf(f2.x + bbA), tanhf(f2.y + bbA));
            o1.y = pk2(tanhf(f3.x + bbA), tanhf(f3.y + bbA));
            u64* d = sm + OFF_A1 + tid * PSTR;
            *(ulonglong2*)d       = o0;
            *(ulonglong2*)(d + 2) = o1;
        }
        __syncthreads();

        // ---- Phase B: partial f_ode[f][2kp..] = sum_{j in quarter} A1[f][j]*W2t[j][2kp..]
        {
            const int j0 = jq * 64;
            const float2* w = (const float2*)g_W2t + kp;   // stride 64 float2 per j
            float2 buf[8];
            #pragma unroll
            for (int u = 0; u < 8; u++) buf[u] = __ldg(w + (j0 + u) * 64);
            u64 a0[4], a1v[4];
            #pragma unroll
            for (int i = 0; i < 4; i++) { a0[i] = 0ull; a1v[i] = 0ull; }
            for (int jj = 0; jj < 64; jj += 8) {
                #pragma unroll
                for (int u = 0; u < 8; u++) {
                    float2 wv = buf[u];
                    buf[u] = __ldg(w + (j0 + jj + u + 8) * 64);    // ring prefetch (padded)
                    u64 w0 = pk2(wv.x, wv.x), w1 = pk2(wv.y, wv.y);
                    const u64* ar = sm + OFF_A1 + (j0 + jj + u) * PSTR;
                    ulonglong2 hA = *(const ulonglong2*)ar;
                    ulonglong2 hB = *(const ulonglong2*)(ar + 2);
                    a0[0] = fma2(hA.x, w0, a0[0]);  a1v[0] = fma2(hA.x, w1, a1v[0]);
                    a0[1] = fma2(hA.y, w0, a0[1]);  a1v[1] = fma2(hA.y, w1, a1v[1]);
                    a0[2] = fma2(hB.x, w0, a0[2]);  a1v[2] = fma2(hB.x, w1, a1v[2]);
                    a0[3] = fma2(hB.y, w0, a0[3]);  a1v[3] = fma2(hB.y, w1, a1v[3]);
                }
            }
            u64* d = sm + OFF_SC + jq * BP_BLK + kp * 10;
            {
                ulonglong2 s; s.x = a0[0]; s.y = a0[1]; *(ulonglong2*)(d) = s;
            }
            {
                ulonglong2 s; s.x = a0[2]; s.y = a0[3]; *(ulonglong2*)(d + 2) = s;
            }
            {
                ulonglong2 s; s.x = a1v[0]; s.y = a1v[1]; *(ulonglong2*)(d + 4) = s;
            }
            {
                ulonglong2 s; s.x = a1v[2]; s.y = a1v[3]; *(ulonglong2*)(d + 6) = s;
            }
        }
        __syncthreads();

        // ---- ODE update: h += dt * (sum of 4 B-partials + b2)
        {
            const int kk = tid >> 1, ph = tid & 1;
            const u64* bp = sm + OFF_SC + (kk >> 1) * 10 + (kk & 1) * 4 + ph * 2;
            ulonglong2 x0 = *(const ulonglong2*)bp;
            ulonglong2 y0 = *(const ulonglong2*)(bp + BP_BLK);
            ulonglong2 z0 = *(const ulonglong2*)(bp + 2 * BP_BLK);
            ulonglong2 u0 = *(const ulonglong2*)(bp + 3 * BP_BLK);
            u64 s0 = add2(add2(x0.x, y0.x), add2(z0.x, u0.x));
            u64 s1 = add2(add2(x0.y, y0.y), add2(z0.y, u0.y));
            u64* hp = sm + OFF_HS + kk * PSTR + ph * 2;
            ulonglong2 h01 = *(const ulonglong2*)hp;
            float2 hv, sv;
            sv = up2(s0); hv = up2(h01.x);
            hv.x = fmaf(dt, sv.x + bbO, hv.x); hv.y = fmaf(dt, sv.y + bbO, hv.y);
            h01.x = pk2(hv.x, hv.y);
            sv = up2(s1); hv = up2(h01.y);
            hv.x = fmaf(dt, sv.x + bbO, hv.x); hv.y = fmaf(dt, sv.y + bbO, hv.y);
            h01.y = pk2(hv.x, hv.y);
            *(ulonglong2*)hp = h01;
        }
        __syncthreads();

        // ---- Phase C: partial gh[f][g] for g = p, p+128, p+256 over k-half
        {
            const int k0 = kh * 64;
            const float* w = g_Wht + p;
            float br0[4], br1[4], br2[4];
            #pragma unroll
            for (int u = 0; u < 4; u++) {
                const float* wr = w + (k0 + u) * GG;
                br0[u] = __ldg(wr); br1[u] = __ldg(wr + 128); br2[u] = __ldg(wr + 256);
            }
            u64 ar[4], az[4], an[4];
            #pragma unroll
            for (int i = 0; i < 4; i++) { ar[i] = 0ull; az[i] = 0ull; an[i] = 0ull; }
            for (int kk2 = 0; kk2 < 64; kk2 += 4) {
                #pragma unroll
                for (int u = 0; u < 4; u++) {
                    float w0f = br0[u], w1f = br1[u], w2f = br2[u];
                    const float* wr = w + (k0 + kk2 + u + 4) * GG;   // ring prefetch (padded)
                    br0[u] = __ldg(wr); br1[u] = __ldg(wr + 128); br2[u] = __ldg(wr + 256);
                    u64 w0 = pk2(w0f, w0f), w1 = pk2(w1f, w1f), w2 = pk2(w2f, w2f);
                    const u64* hr = sm + OFF_HS + (k0 + kk2 + u) * PSTR;
                    ulonglong2 hA = *(const ulonglong2*)hr;
                    ulonglong2 hB = *(const ulonglong2*)(hr + 2);
                    ar[0] = fma2(hA.x, w0, ar[0]); az[0] = fma2(hA.x, w1, az[0]); an[0] = fma2(hA.x, w2, an[0]);
                    ar[1] = fma2(hA.y, w0, ar[1]); az[1] = fma2(hA.y, w1, az[1]); an[1] = fma2(hA.y, w2, an[1]);
                    ar[2] = fma2(hB.x, w0, ar[2]); az[2] = fma2(hB.x, w1, az[2]); an[2] = fma2(hB.x, w2, an[2]);
                    ar[3] = fma2(hB.y, w0, ar[3]); az[3] = fma2(hB.y, w1, az[3]); an[3] = fma2(hB.y, w2, an[3]);
                }
            }
            u64* d = sm + OFF_SC + kh * CP_BLK + p * 16;
            {
                ulonglong2 s; s.x = ar[0]; s.y = ar[1]; *(ulonglong2*)(d) = s;
            }
            {
                ulonglong2 s; s.x = ar[2]; s.y = ar[3]; *(ulonglong2*)(d + 2) = s;
            }
            {
                ulonglong2 s; s.x = az[0]; s.y = az[1]; *(ulonglong2*)(d + 4) = s;
            }
            {
                ulonglong2 s; s.x = az[2]; s.y = az[3]; *(ulonglong2*)(d + 6) = s;
            }
            {
                ulonglong2 s; s.x = an[0]; s.y = an[1]; *(ulonglong2*)(d + 8) = s;
            }
            {
                ulonglong2 s; s.x = an[2]; s.y = an[3]; *(ulonglong2*)(d + 10) = s;
            }
        }
        __syncthreads();

        // ---- GRU gates + mask update (reduces C partials inline)
        {
            const int b0 = OFF_SC + p * 16;
            #pragma unroll
            for (int q = 0; q < 2; q++) {
                const int fp = fh * 2 + q;
                float2 ghr = up2(add2(sm[b0 + fp],     sm[b0 + CP_BLK + fp]));
                float2 ghz = up2(add2(sm[b0 + 4 + fp], sm[b0 + CP_BLK + 4 + fp]));
                float2 ghn = up2(add2(sm[b0 + 8 + fp], sm[b0 + CP_BLK + 8 + fp]));
                float2 hv  = up2(sm[OFF_HS + p * PSTR + fp]);
                {
                    float x = xob[2 * fp], m = xms[2 * fp];
                    float rr = sigm(fmaf(x, wir, bir) + ghr.x + brg);
                    float zz = sigm(fmaf(x, wiz, biz) + ghz.x + bzg);
                    float nn = tanhf(fmaf(x, win, binn) + rr * (ghn.x + bng));
                    float hc = (1.0f - zz) * nn + zz * hv.x;
                    hv.x = m * hc + (1.0f - m) * hv.x;
                }
                {
                    float x = xob[2 * fp + 1], m = xms[2 * fp + 1];
                    float rr = sigm(fmaf(x, wir, bir) + ghr.y + brg);
                    float zz = sigm(fmaf(x, wiz, biz) + ghz.y + bzg);
                    float nn = tanhf(fmaf(x, win, binn) + rr * (ghn.y + bng));
                    float hc = (1.0f - zz) * nn + zz * hv.y;
                    hv.y = m * hc + (1.0f - m) * hv.y;
                }
                sm[OFF_HS + p * PSTR + fp] = pk2(hv.x, hv.y);
            }
        }
        __syncthreads();
    }

    // ---- store final h : out[f_global][k]
    const float* hf = (const float*)(sm + OFF_HS);   // float idx: k*(2*PSTR) + f
    for (int idx = tid; idx < NF * LL; idx += NTH) {
        int f = idx >> 7, k = idx & 127;
        out[(cta * NF + f) * LL + k] = hf[k * 2 * PSTR + f];
    }
}

extern "C" void kernel_launch(void* const* d_in, const int* in_sizes, int n_in,
                              void* d_out, int out_size) {
    const float* times = (const float*)d_in[0];
    const float* vals  = (const float*)d_in[1];
    const float* mask  = (const float*)d_in[2];
    const float* W1    = (const float*)d_in[3];
    const float* b1    = (const float*)d_in[4];
    const float* W2    = (const float*)d_in[5];
    const float* b2    = (const float*)d_in[6];
    const float* Wih   = (const float*)d_in[7];
    const float* bih   = (const float*)d_in[8];
    const float* Whh   = (const float*)d_in[9];
    const float* bhh   = (const float*)d_in[10];
    float* out = (float*)d_out;

    (void)in_sizes; (void)n_in; (void)out_size;

    cudaFuncSetAttribute(odernn_kernel,
                         cudaFuncAttributeMaxDynamicSharedMemorySize, SMEM_BYTES);

    prep_kernel<<<(GG * LL + 255) / 256, 256>>>(W1, W2, Whh);
    odernn_kernel<<<NCTA, NTH, SMEM_BYTES>>>(times, vals, mask, b1, b2,
                                             Wih, bih, bhh, out);
}

// round 9
// speedup vs baseline: 1.2129x; 1.2129x over previous
#include <cuda_runtime.h>

#define TT   1024
#define FF   2048
#define LL   128
#define HH   256
#define GG   384
#define NF   14            // features per CTA (7 pairs)
#define NTH  256
#define NCTA 147           // ceil(2048/14), one CTA per SM
#define PSTR 10            // pair-stride in u64 (7 pairs + 3 pad, 80B rows: conflict-free)

typedef unsigned long long u64;

// k-major transposed weights, padded for prefetch-ring overrun (no allocation)
__device__ float g_W1t[LL * HH + 2048];   // [k][j]  = W1[j][k]
__device__ float g_W2t[HH * LL + 2048];   // [j][k'] = W2[k'][j]
__device__ float g_Wht[LL * GG + 2048];   // [k][g]  = Whh[g][k]

// shared-memory layout (u64 units)
#define OFF_HS   0                          // h: [k=128][10]   -> 1280
#define OFF_A1   1280                       // A1: [j=256][10]  -> 2560
#define OFF_SC   3840                       // partial scratch
#define AP_BLK   2304                       // A: [kh=2][jp=128][18]
#define BP_BLK   1152                       // B: [jq=4][kp=64][18]
#define CP_BLK   3840                       // C: [kh=2][p=128][30]
#define U64_CNT  11520
#define SMEM_BYTES (U64_CNT * 8 + 64 * 4)   // 92416 B

__device__ __forceinline__ u64 pk2(float lo, float hi) {
    u64 r; asm("mov.b64 %0, {%1, %2};" : "=l"(r) : "f"(lo), "f"(hi)); return r;
}
__device__ __forceinline__ float2 up2(u64 v) {
    float2 r; asm("mov.b64 {%0, %1}, %2;" : "=f"(r.x), "=f"(r.y) : "l"(v)); return r;
}
__device__ __forceinline__ u64 fma2(u64 a, u64 b, u64 c) {
    u64 d; asm("fma.rn.f32x2 %0, %1, %2, %3;" : "=l"(d) : "l"(a), "l"(b), "l"(c)); return d;
}
__device__ __forceinline__ u64 add2(u64 a, u64 b) {
    u64 d; asm("add.rn.f32x2 %0, %1, %2;" : "=l"(d) : "l"(a), "l"(b)); return d;
}
__device__ __forceinline__ float sigm(float x) { return 1.0f / (1.0f + expf(-x)); }

__global__ void prep_kernel(const float* __restrict__ W1,
                            const float* __restrict__ W2,
                            const float* __restrict__ Whh) {
    int i = blockIdx.x * blockDim.x + threadIdx.x;
    if (i < HH * LL) { int j = i / LL, k = i % LL; g_W1t[k * HH + j] = W1[i]; }
    if (i < LL * HH) { int k = i / HH, j = i % HH; g_W2t[j * LL + k] = W2[i]; }
    if (i < GG * LL) { int g = i / LL, k = i % LL; g_Wht[k * GG + g] = Whh[i]; }
}

__global__ __launch_bounds__(NTH, 1)
void odernn_kernel(const float* __restrict__ times,
                   const float* __restrict__ vals,
                   const float* __restrict__ mask,
                   const float* __restrict__ b1,
                   const float* __restrict__ b2,
                   const float* __restrict__ Wih,
                   const float* __restrict__ bih,
                   const float* __restrict__ bhh,
                   float* __restrict__ out)
{
    extern __shared__ u64 sm[];
    float* xob = (float*)(sm + U64_CNT);     // 16
    float* xms = (float*)(sm + U64_CNT) + 16;

    const int tid = threadIdx.x;
    const int cta = blockIdx.x;

    for (int i = tid; i < 128 * PSTR; i += NTH) sm[OFF_HS + i] = 0ull;   // h0 = 0

    // thread-resident constants
    const int jp  = tid & 127;           // phase-A j-pair
    const int kh  = tid >> 7;            // k-half (phases A, C)
    const int kp  = tid & 63;            // phase-B k'-pair
    const int jq  = tid >> 6;            // phase-B j-quarter
    const int p   = tid & 127;           // latent index (C / GRU)
    const int fh  = tid >> 7;            // GRU feature-subset selector
    const float bbA = __ldg(b1 + tid);                    // A-reduce bias
    const float bbO = __ldg(b2 + (tid >> 1));             // ODE bias
    const float brg = __ldg(bhh + p), bzg = __ldg(bhh + p + 128), bng = __ldg(bhh + p + 256);
    const float wir = __ldg(Wih + p), wiz = __ldg(Wih + p + 128), win = __ldg(Wih + p + 256);
    const float bir = __ldg(bih + p), biz = __ldg(bih + p + 128), binn = __ldg(bih + p + 256);
    __syncthreads();

    for (int t = 0; t < TT; t++) {
        if (tid < 16) {
            int fg = cta * NF + tid;
            float xo = 0.0f, xm = 0.0f;
            if (tid < NF && fg < FF) {
                long it = (long)(TT - 1 - t) * FF + fg;
                xo = __ldg(vals + it);
                xm = __ldg(mask + it);
            }
            xob[tid] = xo; xms[tid] = xm;
        }
        float dt = 0.0f;
        if (t > 0) dt = __ldg(times + (TT - t)) - __ldg(times + (TT - 1 - t));

        // ---- Phase A: partial a1[f][2jp..] = sum_{k in half} h[f][k]*W1t[k][2jp..]
        {
            const int k0 = kh * 64;
            const float2* w = (const float2*)g_W1t + jp;   // stride 128 float2 per k
            float2 buf[8];
            #pragma unroll
            for (int u = 0; u < 8; u++) buf[u] = __ldg(w + (k0 + u) * 128);
            u64 a0[7], a1v[7];
            #pragma unroll
            for (int i = 0; i < 7; i++) { a0[i] = 0ull; a1v[i] = 0ull; }
            for (int kk = 0; kk < 64; kk += 8) {
                #pragma unroll
                for (int u = 0; u < 8; u++) {
                    float2 wv = buf[u];
                    buf[u] = __ldg(w + (k0 + kk + u + 8) * 128);   // ring prefetch (padded)
                    u64 w0 = pk2(wv.x, wv.x), w1 = pk2(wv.y, wv.y);
                    const u64* hr = sm + OFF_HS + (k0 + kk + u) * PSTR;
                    ulonglong2 hA = *(const ulonglong2*)hr;
                    ulonglong2 hB = *(const ulonglong2*)(hr + 2);
                    ulonglong2 hC = *(const ulonglong2*)(hr + 4);
                    u64 h6 = hr[6];
                    a0[0] = fma2(hA.x, w0, a0[0]);  a1v[0] = fma2(hA.x, w1, a1v[0]);
                    a0[1] = fma2(hA.y, w0, a0[1]);  a1v[1] = fma2(hA.y, w1, a1v[1]);
                    a0[2] = fma2(hB.x, w0, a0[2]);  a1v[2] = fma2(hB.x, w1, a1v[2]);
                    a0[3] = fma2(hB.y, w0, a0[3]);  a1v[3] = fma2(hB.y, w1, a1v[3]);
                    a0[4] = fma2(hC.x, w0, a0[4]);  a1v[4] = fma2(hC.x, w1, a1v[4]);
                    a0[5] = fma2(hC.y, w0, a0[5]);  a1v[5] = fma2(hC.y, w1, a1v[5]);
                    a0[6] = fma2(h6,   w0, a0[6]);  a1v[6] = fma2(h6,   w1, a1v[6]);
                }
            }
            u64* d = sm + OFF_SC + kh * AP_BLK + jp * 18;
            { ulonglong2 s; s.x = a0[0]; s.y = a0[1]; *(ulonglong2*)(d)     = s; }
            { ulonglong2 s; s.x = a0[2]; s.y = a0[3]; *(ulonglong2*)(d + 2) = s; }
            { ulonglong2 s; s.x = a0[4]; s.y = a0[5]; *(ulonglong2*)(d + 4) = s; }
            d[6] = a0[6];
            { ulonglong2 s; s.x = a1v[0]; s.y = a1v[1]; *(ulonglong2*)(d + 8)  = s; }
            { ulonglong2 s; s.x = a1v[2]; s.y = a1v[3]; *(ulonglong2*)(d + 10) = s; }
            { ulonglong2 s; s.x = a1v[4]; s.y = a1v[5]; *(ulonglong2*)(d + 12) = s; }
            d[14] = a1v[6];
        }
        __syncthreads();

        // ---- A-reduce + tanh -> A1[j][7 pairs]   (j = tid)
        {
            const u64* s0 = sm + OFF_SC + (tid >> 1) * 18 + (tid & 1) * 8;
            ulonglong2 pA = *(const ulonglong2*)s0;
            ulonglong2 pB = *(const ulonglong2*)(s0 + 2);
            ulonglong2 pC = *(const ulonglong2*)(s0 + 4);
            u64 p6 = s0[6];
            ulonglong2 qA = *(const ulonglong2*)(s0 + AP_BLK);
            ulonglong2 qB = *(const ulonglong2*)(s0 + AP_BLK + 2);
            ulonglong2 qC = *(const ulonglong2*)(s0 + AP_BLK + 4);
            u64 q6 = s0[AP_BLK + 6];
            float2 f0 = up2(add2(pA.x, qA.x)), f1 = up2(add2(pA.y, qA.y));
            float2 f2 = up2(add2(pB.x, qB.x)), f3 = up2(add2(pB.y, qB.y));
            float2 f4 = up2(add2(pC.x, qC.x)), f5 = up2(add2(pC.y, qC.y));
            float2 f6 = up2(add2(p6, q6));
            u64* d = sm + OFF_A1 + tid * PSTR;
            { ulonglong2 o; o.x = pk2(tanhf(f0.x + bbA), tanhf(f0.y + bbA));
                            o.y = pk2(tanhf(f1.x + bbA), tanhf(f1.y + bbA));
              *(ulonglong2*)d = o; }
            { ulonglong2 o; o.x = pk2(tanhf(f2.x + bbA), tanhf(f2.y + bbA));
                            o.y = pk2(tanhf(f3.x + bbA), tanhf(f3.y + bbA));
              *(ulonglong2*)(d + 2) = o; }
            { ulonglong2 o; o.x = pk2(tanhf(f4.x + bbA), tanhf(f4.y + bbA));
                            o.y = pk2(tanhf(f5.x + bbA), tanhf(f5.y + bbA));
              *(ulonglong2*)(d + 4) = o; }
            d[6] = pk2(tanhf(f6.x + bbA), tanhf(f6.y + bbA));
        }
        __syncthreads();

        // ---- Phase B: partial f_ode[f][2kp..] = sum_{j in quarter} A1[f][j]*W2t[j][2kp..]
        {
            const int j0 = jq * 64;
            const float2* w = (const float2*)g_W2t + kp;   // stride 64 float2 per j
            float2 buf[8];
            #pragma unroll
            for (int u = 0; u < 8; u++) buf[u] = __ldg(w + (j0 + u) * 64);
            u64 a0[7], a1v[7];
            #pragma unroll
            for (int i = 0; i < 7; i++) { a0[i] = 0ull; a1v[i] = 0ull; }
            for (int jj = 0; jj < 64; jj += 8) {
                #pragma unroll
                for (int u = 0; u < 8; u++) {
                    float2 wv = buf[u];
                    buf[u] = __ldg(w + (j0 + jj + u + 8) * 64);    // ring prefetch (padded)
                    u64 w0 = pk2(wv.x, wv.x), w1 = pk2(wv.y, wv.y);
                    const u64* ar = sm + OFF_A1 + (j0 + jj + u) * PSTR;
                    ulonglong2 hA = *(const ulonglong2*)ar;
                    ulonglong2 hB = *(const ulonglong2*)(ar + 2);
                    ulonglong2 hC = *(const ulonglong2*)(ar + 4);
                    u64 h6 = ar[6];
                    a0[0] = fma2(hA.x, w0, a0[0]);  a1v[0] = fma2(hA.x, w1, a1v[0]);
                    a0[1] = fma2(hA.y, w0, a0[1]);  a1v[1] = fma2(hA.y, w1, a1v[1]);
                    a0[2] = fma2(hB.x, w0, a0[2]);  a1v[2] = fma2(hB.x, w1, a1v[2]);
                    a0[3] = fma2(hB.y, w0, a0[3]);  a1v[3] = fma2(hB.y, w1, a1v[3]);
                    a0[4] = fma2(hC.x, w0, a0[4]);  a1v[4] = fma2(hC.x, w1, a1v[4]);
                    a0[5] = fma2(hC.y, w0, a0[5]);  a1v[5] = fma2(hC.y, w1, a1v[5]);
                    a0[6] = fma2(h6,   w0, a0[6]);  a1v[6] = fma2(h6,   w1, a1v[6]);
                }
            }
            u64* d = sm + OFF_SC + jq * BP_BLK + kp * 18;
            { ulonglong2 s; s.x = a0[0]; s.y = a0[1]; *(ulonglong2*)(d)     = s; }
            { ulonglong2 s; s.x = a0[2]; s.y = a0[3]; *(ulonglong2*)(d + 2) = s; }
            { ulonglong2 s; s.x = a0[4]; s.y = a0[5]; *(ulonglong2*)(d + 4) = s; }
            d[6] = a0[6];
            { ulonglong2 s; s.x = a1v[0]; s.y = a1v[1]; *(ulonglong2*)(d + 8)  = s; }
            { ulonglong2 s; s.x = a1v[2]; s.y = a1v[3]; *(ulonglong2*)(d + 10) = s; }
            { ulonglong2 s; s.x = a1v[4]; s.y = a1v[5]; *(ulonglong2*)(d + 12) = s; }
            d[14] = a1v[6];
        }
        __syncthreads();

        // ---- ODE update: h += dt * (sum of 4 B-partials + b2)
        {
            const int kk = tid >> 1, ph = tid & 1;
            const u64* base = sm + OFF_SC + (kk >> 1) * 18 + (kk & 1) * 8;
            u64* hrow = sm + OFF_HS + kk * PSTR;
            if (ph == 0) {
                // feature-pairs 0..3
                ulonglong2 xA = *(const ulonglong2*)base;
                ulonglong2 xB = *(const ulonglong2*)(base + 2);
                ulonglong2 yA = *(const ulonglong2*)(base + BP_BLK);
                ulonglong2 yB = *(const ulonglong2*)(base + BP_BLK + 2);
                ulonglong2 zA = *(const ulonglong2*)(base + 2 * BP_BLK);
                ulonglong2 zB = *(const ulonglong2*)(base + 2 * BP_BLK + 2);
                ulonglong2 uA = *(const ulonglong2*)(base + 3 * BP_BLK);
                ulonglong2 uB = *(const ulonglong2*)(base + 3 * BP_BLK + 2);
                u64 s0 = add2(add2(xA.x, yA.x), add2(zA.x, uA.x));
                u64 s1 = add2(add2(xA.y, yA.y), add2(zA.y, uA.y));
                u64 s2 = add2(add2(xB.x, yB.x), add2(zB.x, uB.x));
                u64 s3 = add2(add2(xB.y, yB.y), add2(zB.y, uB.y));
                ulonglong2 h01 = *(const ulonglong2*)hrow;
                ulonglong2 h23 = *(const ulonglong2*)(hrow + 2);
                float2 hv, sv;
                sv = up2(s0); hv = up2(h01.x);
                hv.x = fmaf(dt, sv.x + bbO, hv.x); hv.y = fmaf(dt, sv.y + bbO, hv.y);
                h01.x = pk2(hv.x, hv.y);
                sv = up2(s1); hv = up2(h01.y);
                hv.x = fmaf(dt, sv.x + bbO, hv.x); hv.y = fmaf(dt, sv.y + bbO, hv.y);
                h01.y = pk2(hv.x, hv.y);
                sv = up2(s2); hv = up2(h23.x);
                hv.x = fmaf(dt, sv.x + bbO, hv.x); hv.y = fmaf(dt, sv.y + bbO, hv.y);
                h23.x = pk2(hv.x, hv.y);
                sv = up2(s3); hv = up2(h23.y);
                hv.x = fmaf(dt, sv.x + bbO, hv.x); hv.y = fmaf(dt, sv.y + bbO, hv.y);
                h23.y = pk2(hv.x, hv.y);
                *(ulonglong2*)hrow       = h01;
                *(ulonglong2*)(hrow + 2) = h23;
            } else {
                // feature-pairs 4..6
                const u64* bp = base + 4;
                ulonglong2 xA = *(const ulonglong2*)bp;            u64 x6 = bp[2];
                ulonglong2 yA = *(const ulonglong2*)(bp + BP_BLK); u64 y6 = bp[BP_BLK + 2];
                ulonglong2 zA = *(const ulonglong2*)(bp + 2 * BP_BLK); u64 z6 = bp[2 * BP_BLK + 2];
                ulonglong2 uA = *(const ulonglong2*)(bp + 3 * BP_BLK); u64 u6 = bp[3 * BP_BLK + 2];
                u64 s0 = add2(add2(xA.x, yA.x), add2(zA.x, uA.x));
                u64 s1 = add2(add2(xA.y, yA.y), add2(zA.y, uA.y));
                u64 s2 = add2(add2(x6, y6), add2(z6, u6));
                ulonglong2 h45 = *(const ulonglong2*)(hrow + 4);
                u64 h6 = hrow[6];
                float2 hv, sv;
                sv = up2(s0); hv = up2(h45.x);
                hv.x = fmaf(dt, sv.x + bbO, hv.x); hv.y = fmaf(dt, sv.y + bbO, hv.y);
                h45.x = pk2(hv.x, hv.y);
                sv = up2(s1); hv = up2(h45.y);
                hv.x = fmaf(dt, sv.x + bbO, hv.x); hv.y = fmaf(dt, sv.y + bbO, hv.y);
                h45.y = pk2(hv.x, hv.y);
                sv = up2(s2); hv = up2(h6);
                hv.x = fmaf(dt, sv.x + bbO, hv.x); hv.y = fmaf(dt, sv.y + bbO, hv.y);
                h6 = pk2(hv.x, hv.y);
                *(ulonglong2*)(hrow + 4) = h45;
                hrow[6] = h6;
            }
        }
        __syncthreads();

        // ---- Phase C: partial gh[f][g] for g = p, p+128, p+256 over k-half
        {
            const int k0 = kh * 64;
            const float* w = g_Wht + p;
            float br0[4], br1[4], br2[4];
            #pragma unroll
            for (int u = 0; u < 4; u++) {
                const float* wr = w + (k0 + u) * GG;
                br0[u] = __ldg(wr); br1[u] = __ldg(wr + 128); br2[u] = __ldg(wr + 256);
            }
            u64 ar[7], az[7], an[7];
            #pragma unroll
            for (int i = 0; i < 7; i++) { ar[i] = 0ull; az[i] = 0ull; an[i] = 0ull; }
            for (int kk2 = 0; kk2 < 64; kk2 += 4) {
                #pragma unroll
                for (int u = 0; u < 4; u++) {
                    float w0f = br0[u], w1f = br1[u], w2f = br2[u];
                    const float* wr = w + (k0 + kk2 + u + 4) * GG;   // ring prefetch (padded)
                    br0[u] = __ldg(wr); br1[u] = __ldg(wr + 128); br2[u] = __ldg(wr + 256);
                    u64 w0 = pk2(w0f, w0f), w1 = pk2(w1f, w1f), w2 = pk2(w2f, w2f);
                    const u64* hr = sm + OFF_HS + (k0 + kk2 + u) * PSTR;
                    ulonglong2 hA = *(const ulonglong2*)hr;
                    ulonglong2 hB = *(const ulonglong2*)(hr + 2);
                    ulonglong2 hC = *(const ulonglong2*)(hr + 4);
                    u64 h6 = hr[6];
                    ar[0] = fma2(hA.x, w0, ar[0]); az[0] = fma2(hA.x, w1, az[0]); an[0] = fma2(hA.x, w2, an[0]);
                    ar[1] = fma2(hA.y, w0, ar[1]); az[1] = fma2(hA.y, w1, az[1]); an[1] = fma2(hA.y, w2, an[1]);
                    ar[2] = fma2(hB.x, w0, ar[2]); az[2] = fma2(hB.x, w1, az[2]); an[2] = fma2(hB.x, w2, an[2]);
                    ar[3] = fma2(hB.y, w0, ar[3]); az[3] = fma2(hB.y, w1, az[3]); an[3] = fma2(hB.y, w2, an[3]);
                    ar[4] = fma2(hC.x, w0, ar[4]); az[4] = fma2(hC.x, w1, az[4]); an[4] = fma2(hC.x, w2, an[4]);
                    ar[5] = fma2(hC.y, w0, ar[5]); az[5] = fma2(hC.y, w1, az[5]); an[5] = fma2(hC.y, w2, an[5]);
                    ar[6] = fma2(h6,   w0, ar[6]); az[6] = fma2(h6,   w1, az[6]); an[6] = fma2(h6,   w2, an[6]);
                }
            }
            u64* d = sm + OFF_SC + kh * CP_BLK + p * 30;
            { ulonglong2 s; s.x = ar[0]; s.y = ar[1]; *(ulonglong2*)(d)     = s; }
            { ulonglong2 s; s.x = ar[2]; s.y = ar[3]; *(ulonglong2*)(d + 2) = s; }
            { ulonglong2 s; s.x = ar[4]; s.y = ar[5]; *(ulonglong2*)(d + 4) = s; }
            d[6] = ar[6];
            { ulonglong2 s; s.x = az[0]; s.y = az[1]; *(ulonglong2*)(d + 10) = s; }
            { ulonglong2 s; s.x = az[2]; s.y = az[3]; *(ulonglong2*)(d + 12) = s; }
            { ulonglong2 s; s.x = az[4]; s.y = az[5]; *(ulonglong2*)(d + 14) = s; }
            d[16] = az[6];
            { ulonglong2 s; s.x = an[0]; s.y = an[1]; *(ulonglong2*)(d + 20) = s; }
            { ulonglong2 s; s.x = an[2]; s.y = an[3]; *(ulonglong2*)(d + 22) = s; }
            { ulonglong2 s; s.x = an[4]; s.y = an[5]; *(ulonglong2*)(d + 24) = s; }
            d[26] = an[6];
        }
        __syncthreads();

        // ---- GRU gates + mask update (reduces C partials inline)
        {
            const int b0 = OFF_SC + p * 30;
            const int f0 = fh ? 4 : 0;
            const int f1 = fh ? 7 : 4;
            for (int fp = f0; fp < f1; fp++) {
                float2 ghr = up2(add2(sm[b0 + fp],      sm[b0 + CP_BLK + fp]));
                float2 ghz = up2(add2(sm[b0 + 10 + fp], sm[b0 + CP_BLK + 10 + fp]));
                float2 ghn = up2(add2(sm[b0 + 20 + fp], sm[b0 + CP_BLK + 20 + fp]));
                float2 hv  = up2(sm[OFF_HS + p * PSTR + fp]);
                {
                    float x = xob[2 * fp], m = xms[2 * fp];
                    float rr = sigm(fmaf(x, wir, bir) + ghr.x + brg);
                    float zz = sigm(fmaf(x, wiz, biz) + ghz.x + bzg);
                    float nn = tanhf(fmaf(x, win, binn) + rr * (ghn.x + bng));
                    float hc = (1.0f - zz) * nn + zz * hv.x;
                    hv.x = m * hc + (1.0f - m) * hv.x;
                }
                {
                    float x = xob[2 * fp + 1], m = xms[2 * fp + 1];
                    float rr = sigm(fmaf(x, wir, bir) + ghr.y + brg);
                    float zz = sigm(fmaf(x, wiz, biz) + ghz.y + bzg);
                    float nn = tanhf(fmaf(x, win, binn) + rr * (ghn.y + bng));
                    float hc = (1.0f - zz) * nn + zz * hv.y;
                    hv.y = m * hc + (1.0f - m) * hv.y;
                }
                sm[OFF_HS + p * PSTR + fp] = pk2(hv.x, hv.y);
            }
        }
        __syncthreads();
    }

    // ---- store final h : out[f_global][k]
    const float* hf = (const float*)(sm + OFF_HS);   // float idx: k*(2*PSTR) + f
    for (int idx = tid; idx < NF * LL; idx += NTH) {
        int f = idx >> 7, k = idx & 127;
        int fg = cta * NF + f;
        if (fg < FF) out[fg * LL + k] = hf[k * 2 * PSTR + f];
    }
}

extern "C" void kernel_launch(void* const* d_in, const int* in_sizes, int n_in,
                              void* d_out, int out_size) {
    const float* times = (const float*)d_in[0];
    const float* vals  = (const float*)d_in[1];
    const float* mask  = (const float*)d_in[2];
    const float* W1    = (const float*)d_in[3];
    const float* b1    = (const float*)d_in[4];
    const float* W2    = (const float*)d_in[5];
    const float* b2    = (const float*)d_in[6];
    const float* Wih   = (const float*)d_in[7];
    const float* bih   = (const float*)d_in[8];
    const float* Whh   = (const float*)d_in[9];
    const float* bhh   = (const float*)d_in[10];
    float* out = (float*)d_out;

    (void)in_sizes; (void)n_in; (void)out_size;

    cudaFuncSetAttribute(odernn_kernel,
                         cudaFuncAttributeMaxDynamicSharedMemorySize, SMEM_BYTES);

    prep_kernel<<<(GG * LL + 255) / 256, 256>>>(W1, W2, Whh);
    odernn_kernel<<<NCTA, NTH, SMEM_BYTES>>>(times, vals, mask, b1, b2,
                                             Wih, bih, bhh, out);
}